// round 5
// baseline (speedup 1.0000x reference)
#include <cuda_runtime.h>
#include <math.h>
#include <stdint.h>

#define NN 5000
#define NE 100000

// ---------------- device scratch ----------------
__device__ float  g_x[NN * 128];
__device__ float  g_Meff[16 * 256];
__device__ int    g_cnt[NN];
__device__ int    g_cur[NN];
__device__ int    g_off[NN + 1];
__device__ int    g_perm[NE];
__device__ float4 g_A[(size_t)NE * 128];     // per (pos,u): w4[l]*gate*xj
__device__ float2 g_gw[(size_t)NE * 128];    // {gate, wm1*xj}
__device__ float4 g_mmd[NE];                 // {mmsh1,mmsh2,mmsh3,dens}
__device__ float  g_msgP[(size_t)(NN / 2) * 2048 * 2];  // node-pair interleaved
__device__ float  g_mmP[(size_t)(NN / 2) * 512 * 2];
__device__ float  g_Wt[4 * 128 * 128 * 12];   // Wsk transposed, z-contig pad12
__device__ float  g_Wmt[2 * 128 * 128 * 12];  // Wmsk l0,l1 transposed

__device__ __forceinline__ float silu_f(float x) { return x / (1.0f + __expf(-x)); }
__device__ __forceinline__ float2 f2(float a, float b) { return make_float2(a, b); }
__device__ __forceinline__ float2 make2(float x) { return make_float2(x, x); }
__device__ __forceinline__ float2 ffma2(float2 a, float2 b, float2 c) {
    unsigned long long ra = *reinterpret_cast<unsigned long long*>(&a);
    unsigned long long rb = *reinterpret_cast<unsigned long long*>(&b);
    unsigned long long rc = *reinterpret_cast<unsigned long long*>(&c);
    unsigned long long rd;
    asm("fma.rn.f32x2 %0, %1, %2, %3;" : "=l"(rd) : "l"(ra), "l"(rb), "l"(rc));
    return *reinterpret_cast<float2*>(&rd);
}
__device__ __forceinline__ float2 dot10(const float2* ap, float4 A, float4 B, float4 C) {
    float2 s = make_float2(0.f, 0.f);
    s = ffma2(ap[0], make2(A.x), s); s = ffma2(ap[1], make2(A.y), s);
    s = ffma2(ap[2], make2(A.z), s); s = ffma2(ap[3], make2(A.w), s);
    s = ffma2(ap[4], make2(B.x), s); s = ffma2(ap[5], make2(B.y), s);
    s = ffma2(ap[6], make2(B.z), s); s = ffma2(ap[7], make2(B.w), s);
    s = ffma2(ap[8], make2(C.x), s); s = ffma2(ap[9], make2(C.y), s);
    return s;
}

// ---------------- setup kernels ----------------
__global__ void k_zero() {
    int i = blockIdx.x * blockDim.x + threadIdx.x;
    if (i < NN) { g_cnt[i] = 0; g_cur[i] = 0; }
}

__global__ void k_meff(const float* __restrict__ M1, const float* __restrict__ M2,
                       const float* __restrict__ M3, const float* __restrict__ M4) {
    __shared__ float T1[16 * 64];
    __shared__ float T2[16 * 64];
    int t = threadIdx.x;
    for (int idx = t; idx < 16 * 64; idx += 256) {
        int a = idx >> 6, k = idx & 63;
        float s = 0.f;
        for (int b = 0; b < 64; b++) s += M1[a * 64 + b] * M2[b * 64 + k];
        T1[idx] = s;
    }
    __syncthreads();
    for (int idx = t; idx < 16 * 64; idx += 256) {
        int a = idx >> 6, k = idx & 63;
        float s = 0.f;
        for (int b = 0; b < 64; b++) s += T1[a * 64 + b] * M3[b * 64 + k];
        T2[idx] = s;
    }
    __syncthreads();
    for (int idx = t; idx < 16 * 256; idx += 256) {
        int a = idx >> 8, c = idx & 255;
        float s = 0.f;
        for (int b = 0; b < 64; b++) s += T2[a * 64 + b] * M4[b * 256 + c];
        g_Meff[idx] = s * 4.8828125e-4f;
    }
}

__global__ void k_x(const float* __restrict__ nf, const float* __restrict__ Wup) {
    __shared__ float s[128];
    int n = blockIdx.x, t = threadIdx.x;
    s[t] = nf[n * 128 + t];
    __syncthreads();
    float acc = 0.f;
#pragma unroll 8
    for (int u = 0; u < 128; u++) acc += s[u] * Wup[u * 128 + t];
    g_x[n * 128 + t] = acc * 0.08838834764831845f;
}

__global__ void k_hist(const int* __restrict__ ei) {
    int e = blockIdx.x * blockDim.x + threadIdx.x;
    if (e < NE) atomicAdd(&g_cnt[ei[NE + e]], 1);
}

__global__ void k_scan() {
    __shared__ int s[1024];
    int t = threadIdx.x;
    int carry = 0;
    for (int base = 0; base < NN; base += 1024) {
        int i = base + t;
        int c = (i < NN) ? g_cnt[i] : 0;
        s[t] = c;
        __syncthreads();
        for (int d = 1; d < 1024; d <<= 1) {
            int v = (t >= d) ? s[t - d] : 0;
            __syncthreads();
            s[t] += v;
            __syncthreads();
        }
        if (i < NN) g_off[i] = carry + s[t] - c;
        carry += s[1023];
        __syncthreads();
    }
    if (t == 0) g_off[NN] = NE;
}

__global__ void k_scatter(const int* __restrict__ ei) {
    int e = blockIdx.x * blockDim.x + threadIdx.x;
    if (e < NE) {
        int r = ei[NE + e];
        int k = atomicAdd(&g_cur[r], 1);
        g_perm[g_off[r] + k] = e;
    }
}

// transpose skip weights to z-contiguous (pad z 10->12, zeros)
__global__ void k_wt(const float* __restrict__ Wsk, const float* __restrict__ Wmsk) {
    int i = blockIdx.x * 256 + threadIdx.x;
    if (i < 4 * 128 * 128) {
        int v = i & 127, uu = (i >> 7) & 127, l = i >> 14;
        float* d = &g_Wt[(size_t)i * 12];
#pragma unroll
        for (int z = 0; z < 12; z++)
            d[z] = (z < 10) ? Wsk[(((size_t)l * 128 + uu) * 10 + z) * 128 + v] : 0.f;
    }
    if (i < 2 * 128 * 128) {
        int v = i & 127, uu = (i >> 7) & 127, l = i >> 14;
        float* d = &g_Wmt[(size_t)i * 12];
#pragma unroll
        for (int z = 0; z < 12; z++)
            d[z] = (z < 10) ? Wmsk[(((size_t)l * 128 + uu) * 10 + z) * 128 + v] : 0.f;
    }
}

// ---------------- edge kernel: 8 edges/block, FFMA2 in w4 GEMM ----------------
__global__ void __launch_bounds__(256) k_edge(
    const float* __restrict__ W1, const float* __restrict__ W2,
    const float* __restrict__ W3, const float* __restrict__ W4,
    const float* __restrict__ ea, const float* __restrict__ ef,
    const float* __restrict__ mmi, const float* __restrict__ mma,
    const float* __restrict__ Wd, const int* __restrict__ ei)
{
    __shared__ float s_efT[16][8];     // [j][el]
    __shared__ float s_h1[8][64];
    __shared__ float s_h2[8 * 65];     // padded rows for transposed read
    __shared__ float s_h3T[64][8];     // [j][el]
    __shared__ float s_w4[8][512];
    __shared__ float s_wmm[8][256];
    __shared__ int   s_e[8], s_send[8];
    __shared__ float s_sh0[8], s_mm0[8];

    int t = threadIdx.x;
    int p0 = blockIdx.x * 8;

    if (t < 8) {
        int e = g_perm[p0 + t];
        s_e[t] = e;
        s_send[t] = ei[e];
    }
    __syncthreads();
    if (t < 128) {
        int el = t >> 4, j = t & 15;
        int e = s_e[el], sd = s_send[el];
        s_efT[j][el] = (j < 8) ? ef[e * 8 + j] : mmi[sd * 8 + (j - 8)];
    }
    __syncthreads();
    // layer1
    for (int r = 0; r < 2; r++) {
        int oi = t + 256 * r, el = oi >> 6, i = oi & 63;
        float s = 0.f;
#pragma unroll
        for (int j = 0; j < 16; j++) s += s_efT[j][el] * W1[j * 64 + i];
        s_h1[el][i] = silu_f(s * 0.25f);
    }
    __syncthreads();
    // layer2 -> padded s_h2
    for (int r = 0; r < 2; r++) {
        int oi = t + 256 * r, el = oi >> 6, i = oi & 63;
        float s = 0.f;
#pragma unroll 8
        for (int j = 0; j < 64; j++) s += s_h1[el][j] * W2[j * 64 + i];
        s_h2[el * 65 + i] = silu_f(s * 0.125f);
    }
    __syncthreads();
    // layer3 -> transposed s_h3T (conflict-free stores: el = lane low bits)
    for (int r = 0; r < 2; r++) {
        int oi = t + 256 * r, el = oi & 7, i = oi >> 3;
        float s = 0.f;
#pragma unroll 8
        for (int j = 0; j < 64; j++) s += s_h2[el * 65 + j] * W3[j * 64 + i];
        s_h3T[i][el] = silu_f(s * 0.125f);
    }
    __syncthreads();
    // w4 = h3 @ W4 / 8, thread owns cols 2t,2t+1, FFMA2 over edge pairs
    {
        float2 a0[4], a1[4];
#pragma unroll
        for (int p = 0; p < 4; p++) { a0[p] = make_float2(0.f, 0.f); a1[p] = make_float2(0.f, 0.f); }
#pragma unroll 4
        for (int j = 0; j < 64; j++) {
            float2 w = *(const float2*)&W4[j * 512 + 2 * t];
            float4 h0 = *(const float4*)&s_h3T[j][0];
            float4 h1 = *(const float4*)&s_h3T[j][4];
            float2 hp0 = f2(h0.x, h0.y), hp1 = f2(h0.z, h0.w);
            float2 hp2 = f2(h1.x, h1.y), hp3 = f2(h1.z, h1.w);
            float2 w0 = make2(w.x), w1 = make2(w.y);
            a0[0] = ffma2(hp0, w0, a0[0]); a1[0] = ffma2(hp0, w1, a1[0]);
            a0[1] = ffma2(hp1, w0, a0[1]); a1[1] = ffma2(hp1, w1, a1[1]);
            a0[2] = ffma2(hp2, w0, a0[2]); a1[2] = ffma2(hp2, w1, a1[2]);
            a0[3] = ffma2(hp3, w0, a0[3]); a1[3] = ffma2(hp3, w1, a1[3]);
        }
#pragma unroll
        for (int p = 0; p < 4; p++) {
            s_w4[2 * p][2 * t]         = a0[p].x * 0.125f;
            s_w4[2 * p + 1][2 * t]     = a0[p].y * 0.125f;
            s_w4[2 * p][2 * t + 1]     = a1[p].x * 0.125f;
            s_w4[2 * p + 1][2 * t + 1] = a1[p].y * 0.125f;
        }
    }
    // w_mm = ef_mm @ M_eff, FFMA2 over edge pairs
    {
        float2 ac[4];
#pragma unroll
        for (int p = 0; p < 4; p++) ac[p] = make_float2(0.f, 0.f);
#pragma unroll
        for (int j = 0; j < 16; j++) {
            float2 m = make2(g_Meff[j * 256 + t]);
            float4 e0 = *(const float4*)&s_efT[j][0];
            float4 e1 = *(const float4*)&s_efT[j][4];
            ac[0] = ffma2(f2(e0.x, e0.y), m, ac[0]);
            ac[1] = ffma2(f2(e0.z, e0.w), m, ac[1]);
            ac[2] = ffma2(f2(e1.x, e1.y), m, ac[2]);
            ac[3] = ffma2(f2(e1.z, e1.w), m, ac[3]);
        }
#pragma unroll
        for (int p = 0; p < 4; p++) {
            s_wmm[2 * p][t]     = ac[p].x;
            s_wmm[2 * p + 1][t] = ac[p].y;
        }
    }
    if (t < 8) {
        int el = t;
        int e = s_e[el], sd = s_send[el];
        s_sh0[el] = ea[(size_t)e * 16];
        float q = 0.f;
#pragma unroll
        for (int j = 0; j < 8; j++) q += ef[e * 8 + j] * Wd[j];
        q *= 0.35355339059327373f;
        float4 md;
        md.x = mma[sd * 4 + 1]; md.y = mma[sd * 4 + 2]; md.z = mma[sd * 4 + 3];
        md.w = tanhf(q * q);
        g_mmd[p0 + el] = md;
        s_mm0[el] = mma[sd * 4];
    }
    __syncthreads();
#pragma unroll
    for (int r = 0; r < 4; r++) {
        int pair = t + 256 * r;
        int el = pair >> 7, u = pair & 127;
        int p = p0 + el;
        float xj = g_x[s_send[el] * 128 + u];
        float4 w4 = *(const float4*)&s_w4[el][u * 4];
        float pre = w4.x * xj * s_sh0[el];
        float2 wm = *(const float2*)&s_wmm[el][u * 2];
        float gate = wm.x * pre * xj * s_mm0[el];
        size_t b = (size_t)p * 128 + u;
        g_gw[b] = f2(gate, wm.y * pre * xj);
        float gx = gate * xj;
        float4 A;
        A.x = w4.x * gx; A.y = w4.y * gx; A.z = w4.z * gx; A.w = w4.w * gx;
        g_A[b] = A;
    }
}

// ---------------- aggregation + per-l linear (4 nodes/block) ----------------
__global__ void __launch_bounds__(128) k_agg(const float* __restrict__ ea,
                                             const float* __restrict__ Wlin,
                                             const float* __restrict__ Wmlin)
{
    __shared__ float s_msg[4][128 * 16];
    __shared__ float s_mm[4][128 * 4];
    __shared__ float s_d[4];
    int u = threadIdx.x;
    int n0 = blockIdx.x * 4;
    const float4* EA4 = (const float4*)ea;

    for (int tn = 0; tn < 4; tn++) {
        int n = n0 + tn;
        float acc[16], am[4];
#pragma unroll
        for (int m = 0; m < 16; m++) acc[m] = 0.f;
#pragma unroll
        for (int j = 0; j < 4; j++) am[j] = 0.f;
        float dl = 0.f;
        int pb = g_off[n], pe = g_off[n + 1];
        for (int p = pb; p < pe; p++) {
            int e = __ldg(&g_perm[p]);
            size_t b = (size_t)p * 128 + u;
            float4 A = g_A[b];
            float2 gw = g_gw[b];
            float4 md = __ldg(&g_mmd[p]);
            float4 S0 = __ldg(&EA4[(size_t)e * 4 + 0]);
            float4 S1 = __ldg(&EA4[(size_t)e * 4 + 1]);
            float4 S2 = __ldg(&EA4[(size_t)e * 4 + 2]);
            float4 S3 = __ldg(&EA4[(size_t)e * 4 + 3]);
            acc[0] += A.x * S0.x; acc[1] += A.y * S0.y; acc[2] += A.y * S0.z; acc[3] += A.y * S0.w;
            acc[4] += A.z * S1.x; acc[5] += A.z * S1.y; acc[6] += A.z * S1.z; acc[7] += A.z * S1.w;
            acc[8] += A.z * S2.x; acc[9] += A.w * S2.y; acc[10] += A.w * S2.z; acc[11] += A.w * S2.w;
            acc[12] += A.w * S3.x; acc[13] += A.w * S3.y; acc[14] += A.w * S3.z; acc[15] += A.w * S3.w;
            am[0] += gw.x;
            am[1] += gw.y * md.x; am[2] += gw.y * md.y; am[3] += gw.y * md.z;
            dl += md.w;
        }
#pragma unroll
        for (int m = 0; m < 16; m++) s_msg[tn][u * 16 + m] = acc[m];
#pragma unroll
        for (int j = 0; j < 4; j++) s_mm[tn][u * 4 + j] = am[j];
        if (u == 0) s_d[tn] = dl;
    }
    __syncthreads();

    int v = u;
    float2 lin2[4][8], lmm2[4][2];
#pragma unroll
    for (int tn = 0; tn < 4; tn++) {
#pragma unroll
        for (int k = 0; k < 8; k++) lin2[tn][k] = make_float2(0.f, 0.f);
        lmm2[tn][0] = make_float2(0.f, 0.f);
        lmm2[tn][1] = make_float2(0.f, 0.f);
    }
    for (int uu = 0; uu < 128; uu++) {
        float w0 = Wlin[(0 * 128 + uu) * 128 + v];
        float w1 = Wlin[(1 * 128 + uu) * 128 + v];
        float w2 = Wlin[(2 * 128 + uu) * 128 + v];
        float w3 = Wlin[(3 * 128 + uu) * 128 + v];
        float m0 = Wmlin[(0 * 128 + uu) * 128 + v];
        float m1 = Wmlin[(1 * 128 + uu) * 128 + v];
        float2 p01 = f2(w0, w1), p11 = make2(w1), p22 = make2(w2);
        float2 p23 = f2(w2, w3), p33 = make2(w3);
        float2 q01 = f2(m0, m1), q11 = make2(m1);
#pragma unroll
        for (int tn = 0; tn < 4; tn++) {
            const float4* Q = (const float4*)&s_msg[tn][uu * 16];
            float4 A = Q[0], B = Q[1], C = Q[2], D = Q[3];
            lin2[tn][0] = ffma2(f2(A.x, A.y), p01, lin2[tn][0]);
            lin2[tn][1] = ffma2(f2(A.z, A.w), p11, lin2[tn][1]);
            lin2[tn][2] = ffma2(f2(B.x, B.y), p22, lin2[tn][2]);
            lin2[tn][3] = ffma2(f2(B.z, B.w), p22, lin2[tn][3]);
            lin2[tn][4] = ffma2(f2(C.x, C.y), p23, lin2[tn][4]);
            lin2[tn][5] = ffma2(f2(C.z, C.w), p33, lin2[tn][5]);
            lin2[tn][6] = ffma2(f2(D.x, D.y), p33, lin2[tn][6]);
            lin2[tn][7] = ffma2(f2(D.z, D.w), p33, lin2[tn][7]);
            float4 M = *(const float4*)&s_mm[tn][uu * 4];
            lmm2[tn][0] = ffma2(f2(M.x, M.y), q01, lmm2[tn][0]);
            lmm2[tn][1] = ffma2(f2(M.z, M.w), q11, lmm2[tn][1]);
        }
    }
    const float sL = 0.08838834764831845f;
#pragma unroll
    for (int tn = 0; tn < 4; tn++) {
        int n = n0 + tn, h = n & 1;
        float inv = sL / (s_d[tn] + 1.0f);
        size_t base = ((size_t)(n >> 1) * 2048 + (size_t)v * 16) * 2 + h;
#pragma unroll
        for (int k = 0; k < 8; k++) {
            g_msgP[base + (2 * k) * 2]     = lin2[tn][k].x * inv;
            g_msgP[base + (2 * k + 1) * 2] = lin2[tn][k].y * inv;
        }
        float im = sL * 0.05f;
        size_t b2 = ((size_t)(n >> 1) * 512 + (size_t)v * 4) * 2 + h;
        g_mmP[b2 + 0] = lmm2[tn][0].x * im;
        g_mmP[b2 + 2] = lmm2[tn][0].y * im;
        g_mmP[b2 + 4] = lmm2[tn][1].x * im;
        g_mmP[b2 + 6] = lmm2[tn][1].y * im;
    }
}

// ---------------- skip TP: 8 nodes/block (2 groups), node-pair FFMA2 ----------------
__global__ void __launch_bounds__(256) k_skip(const float* __restrict__ na,
                                              float* __restrict__ out)
{
    int v = threadIdx.x & 127;
    int g = threadIdx.x >> 7;
    int n0 = blockIdx.x * 8 + g * 4;

    float2 atp[2][10];
#pragma unroll
    for (int P = 0; P < 2; P++)
#pragma unroll
        for (int z = 0; z < 10; z++)
            atp[P][z] = f2(__ldg(&na[(n0 + 2 * P) * 10 + z]),
                           __ldg(&na[(n0 + 2 * P + 1) * 10 + z]));

    float2 a1[2][16], a2[2][4];
#pragma unroll
    for (int P = 0; P < 2; P++) {
#pragma unroll
        for (int m = 0; m < 16; m++) a1[P][m] = make_float2(0.f, 0.f);
#pragma unroll
        for (int m = 0; m < 4; m++) a2[P][m] = make_float2(0.f, 0.f);
    }

    for (int uu = 0; uu < 128; uu++) {
        float2 tt[2][4], t2[2][2];
#pragma unroll
        for (int l = 0; l < 4; l++) {
            const float4* W = (const float4*)&g_Wt[(((size_t)l * 128 + uu) * 128 + v) * 12];
            float4 A = __ldg(W), B = __ldg(W + 1), C = __ldg(W + 2);
            tt[0][l] = dot10(atp[0], A, B, C);
            tt[1][l] = dot10(atp[1], A, B, C);
        }
#pragma unroll
        for (int l = 0; l < 2; l++) {
            const float4* W = (const float4*)&g_Wmt[(((size_t)l * 128 + uu) * 128 + v) * 12];
            float4 A = __ldg(W), B = __ldg(W + 1), C = __ldg(W + 2);
            t2[0][l] = dot10(atp[0], A, B, C);
            t2[1][l] = dot10(atp[1], A, B, C);
        }
#pragma unroll
        for (int P = 0; P < 2; P++) {
            size_t pg = (size_t)(n0 >> 1) + P;
            const float4* MQ = (const float4*)&g_msgP[(pg * 2048 + (size_t)uu * 16) * 2];
            float4 q;
            q = __ldg(&MQ[0]);
            a1[P][0] = ffma2(f2(q.x, q.y), tt[P][0], a1[P][0]);
            a1[P][1] = ffma2(f2(q.z, q.w), tt[P][1], a1[P][1]);
            q = __ldg(&MQ[1]);
            a1[P][2] = ffma2(f2(q.x, q.y), tt[P][1], a1[P][2]);
            a1[P][3] = ffma2(f2(q.z, q.w), tt[P][1], a1[P][3]);
            q = __ldg(&MQ[2]);
            a1[P][4] = ffma2(f2(q.x, q.y), tt[P][2], a1[P][4]);
            a1[P][5] = ffma2(f2(q.z, q.w), tt[P][2], a1[P][5]);
            q = __ldg(&MQ[3]);
            a1[P][6] = ffma2(f2(q.x, q.y), tt[P][2], a1[P][6]);
            a1[P][7] = ffma2(f2(q.z, q.w), tt[P][2], a1[P][7]);
            q = __ldg(&MQ[4]);
            a1[P][8] = ffma2(f2(q.x, q.y), tt[P][2], a1[P][8]);
            a1[P][9] = ffma2(f2(q.z, q.w), tt[P][3], a1[P][9]);
            q = __ldg(&MQ[5]);
            a1[P][10] = ffma2(f2(q.x, q.y), tt[P][3], a1[P][10]);
            a1[P][11] = ffma2(f2(q.z, q.w), tt[P][3], a1[P][11]);
            q = __ldg(&MQ[6]);
            a1[P][12] = ffma2(f2(q.x, q.y), tt[P][3], a1[P][12]);
            a1[P][13] = ffma2(f2(q.z, q.w), tt[P][3], a1[P][13]);
            q = __ldg(&MQ[7]);
            a1[P][14] = ffma2(f2(q.x, q.y), tt[P][3], a1[P][14]);
            a1[P][15] = ffma2(f2(q.z, q.w), tt[P][3], a1[P][15]);
            const float4* MM = (const float4*)&g_mmP[(pg * 512 + (size_t)uu * 4) * 2];
            float4 m0 = __ldg(&MM[0]), m1 = __ldg(&MM[1]);
            a2[P][0] = ffma2(f2(m0.x, m0.y), t2[P][0], a2[P][0]);
            a2[P][1] = ffma2(f2(m0.z, m0.w), t2[P][1], a2[P][1]);
            a2[P][2] = ffma2(f2(m1.x, m1.y), t2[P][1], a2[P][2]);
            a2[P][3] = ffma2(f2(m1.z, m1.w), t2[P][1], a2[P][3]);
        }
    }
    const float sc = 0.02795084971874737f;  // 1/sqrt(1280)
#pragma unroll
    for (int P = 0; P < 2; P++) {
#pragma unroll
        for (int h = 0; h < 2; h++) {
            int n = n0 + 2 * P + h;
            size_t ob = ((size_t)n * 128 + v) * 16;
#pragma unroll
            for (int m = 0; m < 16; m++)
                out[ob + m] = (h ? a1[P][m].y : a1[P][m].x) * sc;
            size_t ob2 = (size_t)NN * 2048 + ob;
#pragma unroll
            for (int m = 0; m < 4; m++)
                out[ob2 + m] = (h ? a2[P][m].y : a2[P][m].x) * sc;
#pragma unroll
            for (int m = 4; m < 16; m++) out[ob2 + m] = 0.f;
        }
    }
}

// ---------------- host ----------------
extern "C" void kernel_launch(void* const* d_in, const int* in_sizes, int n_in,
                              void* d_out, int out_size)
{
    const int* ei;
    int wi;
    if (in_sizes[6] == 2 * NE) { ei = (const int*)d_in[6]; wi = 7; }
    else                       { ei = (const int*)d_in[n_in - 1]; wi = 6; }

    const float* na   = (const float*)d_in[0];
    const float* nf   = (const float*)d_in[1];
    const float* ea   = (const float*)d_in[2];
    const float* ef   = (const float*)d_in[3];
    const float* mmi  = (const float*)d_in[4];
    const float* mma  = (const float*)d_in[5];
    const float* Wup  = (const float*)d_in[wi + 0];
    const float* W1   = (const float*)d_in[wi + 1];
    const float* W2   = (const float*)d_in[wi + 2];
    const float* W3   = (const float*)d_in[wi + 3];
    const float* W4   = (const float*)d_in[wi + 4];
    const float* M1   = (const float*)d_in[wi + 5];
    const float* M2   = (const float*)d_in[wi + 6];
    const float* M3   = (const float*)d_in[wi + 7];
    const float* M4   = (const float*)d_in[wi + 8];
    const float* Wd   = (const float*)d_in[wi + 9];
    const float* Wlin = (const float*)d_in[wi + 10];
    const float* Wmlin= (const float*)d_in[wi + 11];
    const float* Wsk  = (const float*)d_in[wi + 12];
    const float* Wmsk = (const float*)d_in[wi + 13];
    float* out = (float*)d_out;

    k_zero<<<(NN + 255) / 256, 256>>>();
    k_meff<<<1, 256>>>(M1, M2, M3, M4);
    k_x<<<NN, 128>>>(nf, Wup);
    k_wt<<<(4 * 128 * 128) / 256, 256>>>(Wsk, Wmsk);
    k_hist<<<(NE + 255) / 256, 256>>>(ei);
    k_scan<<<1, 1024>>>();
    k_scatter<<<(NE + 255) / 256, 256>>>(ei);
    k_edge<<<NE / 8, 256>>>(W1, W2, W3, W4, ea, ef, mmi, mma, Wd, ei);
    k_agg<<<NN / 4, 128>>>(ea, Wlin, Wmlin);
    k_skip<<<NN / 8, 256>>>(na, out);
}